// round 13
// baseline (speedup 1.0000x reference)
#include <cuda_runtime.h>
#include <cuda_bf16.h>
#include <cuda_fp16.h>
#include <cstdint>

#define DIVUP(a,b) (((a)+(b)-1)/(b))

static constexpr int NN = 100000;   // nodes
static constexpr int NE = 1600000;  // edges (divisible by 16)
static constexpr int CI = 512;      // in_channels
static constexpr int CH = 256;      // hidden
static constexpr int CO = 40;       // out_channels
static constexpr int CO_PAD = 64;   // padded out channels for GEMM2

// ---------------- scratch (static device globals; no allocation) ----------------
__device__ __align__(16) __half g_qx[(size_t)NN * CI];     // quantized x levels (fp16)
__device__ __align__(16) __half g_qw1[CH * CI];            // quantized w1 levels (fp16)
__device__ __align__(16) __half g_qw2[CO_PAD * CH];        // quantized w2 levels (fp16)
__device__ __align__(16) __half g_h[(size_t)NN * CH];      // hidden activations (fp16)
__device__ __align__(16) float g_z[(size_t)NN * CO];       // dinv[src]-scaled logits
__device__ __align__(16) float g_accum[(size_t)NN * CO];   // propagation accumulator
__device__ float g_deg[NN];
__device__ float g_dinv[NN];
__device__ int   g_maxbits[4];   // 0:|x| 1:|w1| 2:|w2| 3:|h| (float bits; finalize resets)
// scales: 0:1/sx 1:sx*sw1 2:1/sw1 3:1/sw2 4:1/sh 5:sh*sw2 6:sw2
__device__ float g_scales[8];

__device__ __forceinline__ float qlevel_mul(float x, float inv) {
    float q = rintf(x * inv);
    return fminf(fmaxf(q, -128.0f), 127.0f);
}
__device__ __forceinline__ unsigned packh2(float a, float b) {
    __half2 t = __floats2half2_rn(a, b);
    return *reinterpret_cast<unsigned*>(&t);
}

// ---------------- fused abs-max over x, w1, w2 ----------------
__global__ void absmax_all_kernel(const float* __restrict__ x,
                                  const float* __restrict__ w1,
                                  const float* __restrict__ w2) {
    const size_t stride = (size_t)gridDim.x * blockDim.x;
    const size_t t0 = (size_t)blockIdx.x * blockDim.x + threadIdx.x;
    float m0 = 0.f, m1 = 0.f, m2 = 0.f;
    #pragma unroll 4
    for (size_t i = t0; i < (size_t)NN * CI / 4; i += stride) {
        float4 v = reinterpret_cast<const float4*>(x)[i];
        m0 = fmaxf(m0, fmaxf(fmaxf(fabsf(v.x), fabsf(v.y)), fmaxf(fabsf(v.z), fabsf(v.w))));
    }
    for (size_t i = t0; i < (size_t)CH * CI / 4; i += stride) {
        float4 v = reinterpret_cast<const float4*>(w1)[i];
        m1 = fmaxf(m1, fmaxf(fmaxf(fabsf(v.x), fabsf(v.y)), fmaxf(fabsf(v.z), fabsf(v.w))));
    }
    for (size_t i = t0; i < (size_t)CO * CH / 4; i += stride) {
        float4 v = reinterpret_cast<const float4*>(w2)[i];
        m2 = fmaxf(m2, fmaxf(fmaxf(fabsf(v.x), fabsf(v.y)), fmaxf(fabsf(v.z), fabsf(v.w))));
    }
    #pragma unroll
    for (int o = 16; o > 0; o >>= 1) {
        m0 = fmaxf(m0, __shfl_xor_sync(0xffffffffu, m0, o));
        m1 = fmaxf(m1, __shfl_xor_sync(0xffffffffu, m1, o));
        m2 = fmaxf(m2, __shfl_xor_sync(0xffffffffu, m2, o));
    }
    if ((threadIdx.x & 31) == 0) {
        atomicMax(&g_maxbits[0], __float_as_int(m0));
        if (m1 > 0.f) atomicMax(&g_maxbits[1], __float_as_int(m1));
        if (m2 > 0.f) atomicMax(&g_maxbits[2], __float_as_int(m2));
    }
}

__global__ void finalize1_kernel() {
    float sx  = __int_as_float(g_maxbits[0]) / 127.0f + 1e-12f;
    float sw1 = __int_as_float(g_maxbits[1]) / 127.0f + 1e-12f;
    float sw2 = __int_as_float(g_maxbits[2]) / 127.0f + 1e-12f;
    g_scales[0] = 1.0f / sx;
    g_scales[1] = sx * sw1;
    g_scales[2] = 1.0f / sw1;
    g_scales[3] = 1.0f / sw2;
    g_scales[6] = sw2;
    g_maxbits[0] = 0; g_maxbits[1] = 0; g_maxbits[2] = 0;   // reset for graph replay
}
__global__ void finalize2_kernel() {
    float sh = __int_as_float(g_maxbits[3]) / 127.0f + 1e-12f;
    g_scales[4] = 1.0f / sh;
    g_scales[5] = sh * g_scales[6];
    g_maxbits[3] = 0;                                        // reset for graph replay
}

// ---------------- fused quantization: x,w1,w2 -> fp16 integer levels ----------------
__global__ void quant_all_kernel(const float* __restrict__ x,
                                 const float* __restrict__ w1,
                                 const float* __restrict__ w2) {
    const size_t stride = (size_t)gridDim.x * blockDim.x;
    const size_t t0 = (size_t)blockIdx.x * blockDim.x + threadIdx.x;
    const float invx = g_scales[0], invw1 = g_scales[2], invw2 = g_scales[3];
    #pragma unroll 2
    for (size_t i = t0; i < (size_t)NN * CI / 4; i += stride) {
        float4 v = reinterpret_cast<const float4*>(x)[i];
        uint2 o;
        o.x = packh2(qlevel_mul(v.x, invx), qlevel_mul(v.y, invx));
        o.y = packh2(qlevel_mul(v.z, invx), qlevel_mul(v.w, invx));
        reinterpret_cast<uint2*>(g_qx)[i] = o;
    }
    for (size_t i = t0; i < (size_t)CH * CI / 4; i += stride) {
        float4 v = reinterpret_cast<const float4*>(w1)[i];
        uint2 o;
        o.x = packh2(qlevel_mul(v.x, invw1), qlevel_mul(v.y, invw1));
        o.y = packh2(qlevel_mul(v.z, invw1), qlevel_mul(v.w, invw1));
        reinterpret_cast<uint2*>(g_qw1)[i] = o;
    }
    for (size_t i = t0; i < (size_t)CO_PAD * CH; i += stride) {
        int r = (int)(i / CH), c = (int)(i % CH);
        float v = (r < CO) ? qlevel_mul(w2[r * CH + c], invw2) : 0.0f;
        g_qw2[i] = __float2half_rn(v);
    }
}

// ---------------- GEMM1: fp16 HMMA, 4-stage BK=32 pipeline, 2 CTAs/SM ----------------
// h = relu( (qx @ qw1^T) * sx*sw1 + b1 ), records max|h|.
static constexpr int G1_BM = 64, G1_BN = 256, G1_BK = 32, G1_LDS = 40, G1_ST = 4;
static constexpr int SMEM1 = G1_ST * (G1_BM + G1_BN) * G1_LDS * 2;   // 102400 B

__global__ void __launch_bounds__(256, 2) gemm1_kernel(const float* __restrict__ b1) {
    extern __shared__ __align__(16) char sm[];
    __half* As = reinterpret_cast<__half*>(sm);     // [4][64][40]
    __half* Bs = As + G1_ST * G1_BM * G1_LDS;       // [4][256][40]

    const int tid = threadIdx.x, warp = tid >> 5, lane = tid & 31;
    // 8 warps: 2 (M) x 4 (N); WM=32, WN=64 -> FM=2, FN=8
    const int wm = (warp >> 2) * 32;
    const int wn = (warp & 3) * 64;
    const int m0 = blockIdx.x * G1_BM;

    float acc[2][8][4];
    #pragma unroll
    for (int a = 0; a < 2; a++)
        #pragma unroll
        for (int b = 0; b < 8; b++)
            #pragma unroll
            for (int c = 0; c < 4; c++) acc[a][b][c] = 0.0f;

    auto fillA = [&](int kt, int buf) {
        int r = tid >> 2, c = (tid & 3) * 8;        // 64 rows x 4 16B-chunks = 256
        int gr = m0 + r;
        unsigned d = (unsigned)__cvta_generic_to_shared(As + (buf * G1_BM + r) * G1_LDS + c);
        const __half* g = g_qx + (size_t)(gr < NN ? gr : 0) * CI + kt * G1_BK + c;
        int sz = (gr < NN) ? 16 : 0;
        asm volatile("cp.async.cg.shared.global [%0], [%1], 16, %2;\n"
                     :: "r"(d), "l"(g), "r"(sz));
    };
    auto fillB = [&](int kt, int buf) {
        #pragma unroll
        for (int i = 0; i < 4; i++) {               // 256 rows x 4 chunks = 1024
            int idx = tid + i * 256, r = idx >> 2, c = (idx & 3) * 8;
            unsigned d = (unsigned)__cvta_generic_to_shared(Bs + (buf * G1_BN + r) * G1_LDS + c);
            const __half* g = g_qw1 + (size_t)r * CI + kt * G1_BK + c;
            asm volatile("cp.async.cg.shared.global [%0], [%1], 16;\n" :: "r"(d), "l"(g));
        }
    };

    const int nk = CI / G1_BK;                      // 16 stages
    #pragma unroll
    for (int s = 0; s < 3; s++) {                   // prologue: stages 0..2 in flight
        fillA(s, s); fillB(s, s);
        asm volatile("cp.async.commit_group;\n");
    }

    for (int kt = 0; kt < nk; kt++) {
        const int buf = kt & 3;
        asm volatile("cp.async.wait_group 2;\n");   // stage kt complete
        __syncthreads();
        if (kt + 3 < nk) { fillA(kt + 3, (kt + 3) & 3); fillB(kt + 3, (kt + 3) & 3); }
        asm volatile("cp.async.commit_group;\n");

        const __half* Ab = As + buf * G1_BM * G1_LDS;
        const __half* Bb = Bs + buf * G1_BN * G1_LDS;
        #pragma unroll
        for (int ks = 0; ks < 2; ks++) {            // 2 x k16 per stage
            unsigned af[2][4], bf[8][2];
            #pragma unroll
            for (int fm = 0; fm < 2; fm++) {
                unsigned addr = (unsigned)__cvta_generic_to_shared(
                    Ab + (wm + fm * 16 + (lane & 15)) * G1_LDS + ks * 16 + (lane >> 4) * 8);
                asm volatile("ldmatrix.sync.aligned.m8n8.x4.shared.b16 {%0,%1,%2,%3}, [%4];"
                    : "=r"(af[fm][0]), "=r"(af[fm][1]), "=r"(af[fm][2]), "=r"(af[fm][3])
                    : "r"(addr));
            }
            #pragma unroll
            for (int p = 0; p < 4; p++) {           // n16-pair x4 loads
                unsigned addr = (unsigned)__cvta_generic_to_shared(
                    Bb + (wn + p * 16 + ((lane >> 4) & 1) * 8 + (lane & 7)) * G1_LDS
                       + ks * 16 + ((lane >> 3) & 1) * 8);
                asm volatile("ldmatrix.sync.aligned.m8n8.x4.shared.b16 {%0,%1,%2,%3}, [%4];"
                    : "=r"(bf[2 * p][0]), "=r"(bf[2 * p][1]),
                      "=r"(bf[2 * p + 1][0]), "=r"(bf[2 * p + 1][1])
                    : "r"(addr));
            }
            #pragma unroll
            for (int fm = 0; fm < 2; fm++)
                #pragma unroll
                for (int fn = 0; fn < 8; fn++) {
                    asm volatile(
                        "mma.sync.aligned.m16n8k16.row.col.f32.f16.f16.f32 "
                        "{%0,%1,%2,%3},{%4,%5,%6,%7},{%8,%9},{%0,%1,%2,%3};"
                        : "+f"(acc[fm][fn][0]), "+f"(acc[fm][fn][1]),
                          "+f"(acc[fm][fn][2]), "+f"(acc[fm][fn][3])
                        : "r"(af[fm][0]), "r"(af[fm][1]), "r"(af[fm][2]), "r"(af[fm][3]),
                          "r"(bf[fn][0]), "r"(bf[fn][1]));
                }
        }
    }

    // epilogue: scale+bias+relu, record max|h|, write fp16
    const float cs = g_scales[1];
    float lmax = 0.0f;
    #pragma unroll
    for (int fm = 0; fm < 2; fm++)
        #pragma unroll
        for (int fn = 0; fn < 8; fn++) {
            int col = wn + fn * 8 + (lane & 3) * 2;
            #pragma unroll
            for (int hh = 0; hh < 2; hh++) {
                int gr = m0 + wm + fm * 16 + (lane >> 2) + hh * 8;
                if (gr < NN) {
                    float v0 = acc[fm][fn][hh * 2 + 0] * cs + b1[col];
                    float v1 = acc[fm][fn][hh * 2 + 1] * cs + b1[col + 1];
                    v0 = fmaxf(v0, 0.0f); v1 = fmaxf(v1, 0.0f);
                    lmax = fmaxf(lmax, fmaxf(v0, v1));
                    *reinterpret_cast<__half2*>(g_h + (size_t)gr * CH + col) =
                        __floats2half2_rn(v0, v1);
                }
            }
        }
    #pragma unroll
    for (int o = 16; o > 0; o >>= 1) lmax = fmaxf(lmax, __shfl_xor_sync(0xffffffffu, lmax, o));
    if (lane == 0) atomicMax(&g_maxbits[3], __float_as_int(lmax));
}

// ---------------- GEMM2: fp16 pipe; epilogue folds dinv[src] into z ----------------
static constexpr int G2_BM = 128, G2_BN = 64, G2_BK = 64, G2_LDSH = 72;
static constexpr int SMEM2 = 2 * (G2_BM + G2_BN) * G2_LDSH * 2;   // 55296 B

__global__ void __launch_bounds__(256) gemm2_kernel(const float* __restrict__ b2) {
    extern __shared__ __align__(16) char sm2[];
    __half* As = reinterpret_cast<__half*>(sm2);          // [2][128][72]
    __half* Bs = As + 2 * G2_BM * G2_LDSH;                 // [2][64][72]

    const int tid = threadIdx.x, warp = tid >> 5, lane = tid & 31;
    const int wm = (warp >> 1) * 32;
    const int wn = (warp & 1) * 32;
    const int m0 = blockIdx.x * G2_BM;
    const float inv_a = g_scales[4];

    uint4 aregh[4];
    float acc[2][4][4];
    #pragma unroll
    for (int a = 0; a < 2; a++)
        #pragma unroll
        for (int b = 0; b < 4; b++)
            #pragma unroll
            for (int c = 0; c < 4; c++) acc[a][b][c] = 0.0f;

    auto loadA = [&](int k0) {
        #pragma unroll
        for (int i = 0; i < 4; i++) {
            int idx = tid + i * 256, r = idx >> 3, c = (idx & 7) << 3, gr = m0 + r;
            aregh[i] = (gr < NN)
                ? *reinterpret_cast<const uint4*>(g_h + (size_t)gr * CH + k0 + c)
                : make_uint4(0u, 0u, 0u, 0u);
        }
    };
    auto storeA = [&](int buf) {
        __half* base = As + buf * G2_BM * G2_LDSH;
        #pragma unroll
        for (int i = 0; i < 4; i++) {
            int idx = tid + i * 256, r = idx >> 3, c = (idx & 7) << 3;
            uint4 u = aregh[i], o;
            unsigned* ui = reinterpret_cast<unsigned*>(&u);
            unsigned* uo = reinterpret_cast<unsigned*>(&o);
            #pragma unroll
            for (int j = 0; j < 4; j++) {
                __half2 hv = *reinterpret_cast<const __half2*>(&ui[j]);
                float2 f = __half22float2(hv);
                uo[j] = packh2(qlevel_mul(f.x, inv_a), qlevel_mul(f.y, inv_a));
            }
            *reinterpret_cast<uint4*>(base + r * G2_LDSH + c) = o;
        }
    };
    auto cpB = [&](int k0, int buf) {
        #pragma unroll
        for (int i = 0; i < 2; i++) {
            int idx = tid + i * 256, r = idx >> 3, c = (idx & 7) << 3;
            unsigned d = (unsigned)__cvta_generic_to_shared(Bs + (buf * G2_BN + r) * G2_LDSH + c);
            const __half* g = g_qw2 + (size_t)r * CH + k0 + c;
            asm volatile("cp.async.cg.shared.global [%0], [%1], 16;\n" :: "r"(d), "l"(g));
        }
    };

    loadA(0);
    cpB(0, 0);
    asm volatile("cp.async.commit_group;\n");

    const int nk = CH / G2_BK;    // 4
    for (int kt = 0; kt < nk; kt++) {
        const int cur = kt & 1;
        storeA(cur);
        asm volatile("cp.async.wait_group 0;\n");
        __syncthreads();
        if (kt + 1 < nk) { loadA((kt + 1) * G2_BK); cpB((kt + 1) * G2_BK, cur ^ 1); }
        asm volatile("cp.async.commit_group;\n");

        const __half* Ab = As + cur * G2_BM * G2_LDSH;
        const __half* Bb = Bs + cur * G2_BN * G2_LDSH;
        #pragma unroll
        for (int ks = 0; ks < 4; ks++) {
            unsigned af[2][4], bf[4][2];
            #pragma unroll
            for (int fm = 0; fm < 2; fm++) {
                unsigned addr = (unsigned)__cvta_generic_to_shared(
                    Ab + (wm + fm * 16 + (lane & 15)) * G2_LDSH + ks * 16 + (lane >> 4) * 8);
                asm volatile("ldmatrix.sync.aligned.m8n8.x4.shared.b16 {%0,%1,%2,%3}, [%4];"
                    : "=r"(af[fm][0]), "=r"(af[fm][1]), "=r"(af[fm][2]), "=r"(af[fm][3])
                    : "r"(addr));
            }
            #pragma unroll
            for (int p = 0; p < 2; p++) {
                unsigned addr = (unsigned)__cvta_generic_to_shared(
                    Bb + (wn + p * 16 + ((lane >> 4) & 1) * 8 + (lane & 7)) * G2_LDSH
                       + ks * 16 + ((lane >> 3) & 1) * 8);
                asm volatile("ldmatrix.sync.aligned.m8n8.x4.shared.b16 {%0,%1,%2,%3}, [%4];"
                    : "=r"(bf[2 * p][0]), "=r"(bf[2 * p][1]),
                      "=r"(bf[2 * p + 1][0]), "=r"(bf[2 * p + 1][1])
                    : "r"(addr));
            }
            #pragma unroll
            for (int fm = 0; fm < 2; fm++)
                #pragma unroll
                for (int fn = 0; fn < 4; fn++) {
                    asm volatile(
                        "mma.sync.aligned.m16n8k16.row.col.f32.f16.f16.f32 "
                        "{%0,%1,%2,%3},{%4,%5,%6,%7},{%8,%9},{%0,%1,%2,%3};"
                        : "+f"(acc[fm][fn][0]), "+f"(acc[fm][fn][1]),
                          "+f"(acc[fm][fn][2]), "+f"(acc[fm][fn][3])
                        : "r"(af[fm][0]), "r"(af[fm][1]), "r"(af[fm][2]), "r"(af[fm][3]),
                          "r"(bf[fn][0]), "r"(bf[fn][1]));
                }
        }
    }

    // z' = (fq(h)@qw2^T * cs + b2) * dinv[row]   (dinv[src] folded here)
    const float cs = g_scales[5];
    #pragma unroll
    for (int fm = 0; fm < 2; fm++)
        #pragma unroll
        for (int fn = 0; fn < 4; fn++) {
            int col = wn + fn * 8 + (lane & 3) * 2;
            #pragma unroll
            for (int hh = 0; hh < 2; hh++) {
                int gr = m0 + wm + fm * 16 + (lane >> 2) + hh * 8;
                if (gr < NN) {
                    float dv = g_dinv[gr];
                    #pragma unroll
                    for (int j = 0; j < 2; j++) {
                        int gc = col + j;
                        if (gc < CO)
                            g_z[(size_t)gr * CO + gc] =
                                (acc[fm][fn][hh * 2 + j] * cs + b2[gc]) * dv;
                    }
                }
            }
        }
}

// ---------------- init for propagation ----------------
__global__ void zero_kernel() {
    int i = blockIdx.x * blockDim.x + threadIdx.x;
    if (i < NN * CO / 4) reinterpret_cast<float4*>(g_accum)[i] = make_float4(0.f, 0.f, 0.f, 0.f);
    if (i < NN) g_deg[i] = 0.0f;
}

// ---------------- graph propagation ----------------
__global__ void degree_kernel(const int* __restrict__ ei) {
    int e = blockIdx.x * blockDim.x + threadIdx.x;
    if (e < NE) atomicAdd(&g_deg[ei[NE + e]], 1.0f);
}
__global__ void dinv_kernel() {
    int i = blockIdx.x * blockDim.x + threadIdx.x;
    if (i < NN) {
        float d = g_deg[i];
        g_dinv[i] = (d > 0.0f) ? rsqrtf(fmaxf(d, 1.0f)) : 0.0f;
    }
}
// Warp-cooperative propagate: 16 edges per warp; 160 (edge, float4) tasks / 32 lanes.
// z already carries dinv[src]; dinv[dst] is applied in logsoftmax.
__global__ void propagate_kernel(const int* __restrict__ ei) {
    int gwarp = (blockIdx.x * blockDim.x + threadIdx.x) >> 5;
    int lane = threadIdx.x & 31;
    int base = gwarp * 16;
    if (base >= NE) return;
    int idxv = ei[((lane < 16) ? 0 : NE) + base + (lane & 15)];
    #pragma unroll
    for (int i = 0; i < 5; i++) {
        int task = lane + 32 * i;  // 0..159
        int e = task / 10, ch = task - e * 10;
        int srce = __shfl_sync(0xffffffffu, idxv, e);
        int dste = __shfl_sync(0xffffffffu, idxv, e + 16);
        float4 v = *reinterpret_cast<const float4*>(g_z + (size_t)srce * CO + ch * 4);
        float* p = g_accum + (size_t)dste * CO + ch * 4;
        asm volatile("red.global.add.v4.f32 [%0], {%1,%2,%3,%4};"
                     :: "l"(p), "f"(v.x), "f"(v.y), "f"(v.z), "f"(v.w)
                     : "memory");
    }
}

// ---------------- log-softmax (warp per node row of 40; applies dinv[dst]) ----------------
__global__ void logsoftmax_kernel(float* __restrict__ out) {
    int gw = (blockIdx.x * blockDim.x + threadIdx.x) >> 5;
    int lane = threadIdx.x & 31;
    if (gw >= NN) return;
    const float dv = g_dinv[gw];
    const float* row = g_accum + (size_t)gw * CO;
    float x1 = row[lane] * dv;
    float x2 = (lane < 8) ? row[32 + lane] * dv : -3.402823466e+38f;
    float m = fmaxf(x1, x2);
    #pragma unroll
    for (int o = 16; o > 0; o >>= 1) m = fmaxf(m, __shfl_xor_sync(0xffffffffu, m, o));
    float s = expf(x1 - m) + ((lane < 8) ? expf(x2 - m) : 0.0f);
    #pragma unroll
    for (int o = 16; o > 0; o >>= 1) s += __shfl_xor_sync(0xffffffffu, s, o);
    float lse = m + logf(s);
    float* o = out + (size_t)gw * CO;
    o[lane] = x1 - lse;
    if (lane < 8) o[32 + lane] = x2 - lse;
}

// ---------------- launch (gemm1 at slot #4 for the ncu capture) ----------------
extern "C" void kernel_launch(void* const* d_in, const int* in_sizes, int n_in,
                              void* d_out, int out_size) {
    const float* x  = (const float*)d_in[0];
    const int*   ei = (const int*)d_in[1];
    const float* w1 = (const float*)d_in[2];
    const float* b1 = (const float*)d_in[3];
    const float* w2 = (const float*)d_in[4];
    const float* b2 = (const float*)d_in[5];
    float* out = (float*)d_out;

    cudaFuncSetAttribute(gemm1_kernel, cudaFuncAttributeMaxDynamicSharedMemorySize, SMEM1);
    cudaFuncSetAttribute(gemm2_kernel, cudaFuncAttributeMaxDynamicSharedMemorySize, SMEM2);

    absmax_all_kernel<<<2048, 256>>>(x, w1, w2);                        // 1
    finalize1_kernel<<<1, 1>>>();                                       // 2
    quant_all_kernel<<<2048, 256>>>(x, w1, w2);                         // 3
    gemm1_kernel<<<DIVUP(NN, G1_BM), 256, SMEM1>>>(b1);                 // 4  <- profiled
    finalize2_kernel<<<1, 1>>>();                                       // 5
    zero_kernel<<<DIVUP(NN * CO / 4, 256), 256>>>();                    // 6
    degree_kernel<<<DIVUP(NE, 256), 256>>>(ei);                         // 7
    dinv_kernel<<<DIVUP(NN, 256), 256>>>();                            // 8
    gemm2_kernel<<<DIVUP(NN, G2_BM), 256, SMEM2>>>(b2);                 // 9 (needs dinv)
    propagate_kernel<<<DIVUP(NE / 16 * 32, 256), 256>>>(ei);            // 10
    logsoftmax_kernel<<<DIVUP(NN * 32, 256), 256>>>(out);               // 11
}

// round 14
// speedup vs baseline: 1.0640x; 1.0640x over previous
#include <cuda_runtime.h>
#include <cuda_bf16.h>
#include <cuda_fp16.h>
#include <cstdint>

#define DIVUP(a,b) (((a)+(b)-1)/(b))

static constexpr int NN = 100000;   // nodes
static constexpr int NE = 1600000;  // edges (divisible by 16)
static constexpr int CI = 512;      // in_channels
static constexpr int CH = 256;      // hidden
static constexpr int CO = 40;       // out_channels
static constexpr int CO_PAD = 64;   // padded out channels for GEMM2

// ---------------- scratch (static device globals; no allocation) ----------------
__device__ __align__(16) __half g_qx[(size_t)NN * CI];     // quantized x levels (fp16)
__device__ __align__(16) __half g_qw1[CH * CI];            // quantized w1 levels (fp16)
__device__ __align__(16) __half g_qw2[CO_PAD * CH];        // quantized w2 levels (fp16)
__device__ __align__(16) __half g_h[(size_t)NN * CH];      // hidden activations (fp16)
__device__ __align__(16) float g_z[(size_t)NN * CO];       // dinv[src]-scaled logits
__device__ __align__(16) float g_accum[(size_t)NN * CO];   // propagation accumulator
__device__ float g_deg[NN];
__device__ float g_dinv[NN];
__device__ int   g_maxbits[4];   // 0:|x| 1:|w1| 2:|w2| 3:|h| (float bits; finalize resets)
// scales: 0:1/sx 1:sx*sw1 2:1/sw1 3:1/sw2 4:1/sh 5:sh*sw2 6:sw2
__device__ float g_scales[8];

__device__ __forceinline__ float qlevel_mul(float x, float inv) {
    float q = rintf(x * inv);
    return fminf(fmaxf(q, -128.0f), 127.0f);
}
__device__ __forceinline__ unsigned packh2(float a, float b) {
    __half2 t = __floats2half2_rn(a, b);
    return *reinterpret_cast<unsigned*>(&t);
}

// ---------------- fused abs-max over x, w1, w2 ----------------
__global__ void absmax_all_kernel(const float* __restrict__ x,
                                  const float* __restrict__ w1,
                                  const float* __restrict__ w2) {
    const size_t stride = (size_t)gridDim.x * blockDim.x;
    const size_t t0 = (size_t)blockIdx.x * blockDim.x + threadIdx.x;
    float m0 = 0.f, m1 = 0.f, m2 = 0.f;
    #pragma unroll 4
    for (size_t i = t0; i < (size_t)NN * CI / 4; i += stride) {
        float4 v = reinterpret_cast<const float4*>(x)[i];
        m0 = fmaxf(m0, fmaxf(fmaxf(fabsf(v.x), fabsf(v.y)), fmaxf(fabsf(v.z), fabsf(v.w))));
    }
    for (size_t i = t0; i < (size_t)CH * CI / 4; i += stride) {
        float4 v = reinterpret_cast<const float4*>(w1)[i];
        m1 = fmaxf(m1, fmaxf(fmaxf(fabsf(v.x), fabsf(v.y)), fmaxf(fabsf(v.z), fabsf(v.w))));
    }
    for (size_t i = t0; i < (size_t)CO * CH / 4; i += stride) {
        float4 v = reinterpret_cast<const float4*>(w2)[i];
        m2 = fmaxf(m2, fmaxf(fmaxf(fabsf(v.x), fabsf(v.y)), fmaxf(fabsf(v.z), fabsf(v.w))));
    }
    #pragma unroll
    for (int o = 16; o > 0; o >>= 1) {
        m0 = fmaxf(m0, __shfl_xor_sync(0xffffffffu, m0, o));
        m1 = fmaxf(m1, __shfl_xor_sync(0xffffffffu, m1, o));
        m2 = fmaxf(m2, __shfl_xor_sync(0xffffffffu, m2, o));
    }
    if ((threadIdx.x & 31) == 0) {
        atomicMax(&g_maxbits[0], __float_as_int(m0));
        if (m1 > 0.f) atomicMax(&g_maxbits[1], __float_as_int(m1));
        if (m2 > 0.f) atomicMax(&g_maxbits[2], __float_as_int(m2));
    }
}

__global__ void finalize1_kernel() {
    float sx  = __int_as_float(g_maxbits[0]) / 127.0f + 1e-12f;
    float sw1 = __int_as_float(g_maxbits[1]) / 127.0f + 1e-12f;
    float sw2 = __int_as_float(g_maxbits[2]) / 127.0f + 1e-12f;
    g_scales[0] = 1.0f / sx;
    g_scales[1] = sx * sw1;
    g_scales[2] = 1.0f / sw1;
    g_scales[3] = 1.0f / sw2;
    g_scales[6] = sw2;
    g_maxbits[0] = 0; g_maxbits[1] = 0; g_maxbits[2] = 0;   // reset for graph replay
}
__global__ void finalize2_kernel() {
    float sh = __int_as_float(g_maxbits[3]) / 127.0f + 1e-12f;
    g_scales[4] = 1.0f / sh;
    g_scales[5] = sh * g_scales[6];
    g_maxbits[3] = 0;                                        // reset for graph replay
}

// ---------------- fused quantization: x,w1,w2 -> fp16 integer levels ----------------
__global__ void quant_all_kernel(const float* __restrict__ x,
                                 const float* __restrict__ w1,
                                 const float* __restrict__ w2) {
    const size_t stride = (size_t)gridDim.x * blockDim.x;
    const size_t t0 = (size_t)blockIdx.x * blockDim.x + threadIdx.x;
    const float invx = g_scales[0], invw1 = g_scales[2], invw2 = g_scales[3];
    #pragma unroll 2
    for (size_t i = t0; i < (size_t)NN * CI / 4; i += stride) {
        float4 v = reinterpret_cast<const float4*>(x)[i];
        uint2 o;
        o.x = packh2(qlevel_mul(v.x, invx), qlevel_mul(v.y, invx));
        o.y = packh2(qlevel_mul(v.z, invx), qlevel_mul(v.w, invx));
        reinterpret_cast<uint2*>(g_qx)[i] = o;
    }
    for (size_t i = t0; i < (size_t)CH * CI / 4; i += stride) {
        float4 v = reinterpret_cast<const float4*>(w1)[i];
        uint2 o;
        o.x = packh2(qlevel_mul(v.x, invw1), qlevel_mul(v.y, invw1));
        o.y = packh2(qlevel_mul(v.z, invw1), qlevel_mul(v.w, invw1));
        reinterpret_cast<uint2*>(g_qw1)[i] = o;
    }
    for (size_t i = t0; i < (size_t)CO_PAD * CH; i += stride) {
        int r = (int)(i / CH), c = (int)(i % CH);
        float v = (r < CO) ? qlevel_mul(w2[r * CH + c], invw2) : 0.0f;
        g_qw2[i] = __float2half_rn(v);
    }
}

// ---------------- GEMM1: fp16 HMMA, BK=64 2-stage, N split, 3 CTAs/SM ----------------
// h = relu( (qx @ qw1^T) * sx*sw1 + b1 ), records max|h|.
// Each CTA computes BM=64 x BN=128 (one n-half); consecutive bids share A rows (L2 reuse).
static constexpr int G1_BM = 64, G1_BN = 128, G1_BK = 64, G1_LDS = 72;
static constexpr int SMEM1 = 2 * (G1_BM + G1_BN) * G1_LDS * 2;   // 55296 B -> 3 CTAs/SM

__global__ void __launch_bounds__(256, 3) gemm1_kernel(const float* __restrict__ b1) {
    extern __shared__ __align__(16) char sm[];
    __half* As = reinterpret_cast<__half*>(sm);     // [2][64][72]
    __half* Bs = As + 2 * G1_BM * G1_LDS;           // [2][128][72]

    const int tid = threadIdx.x, warp = tid >> 5, lane = tid & 31;
    // 8 warps: 2 (M) x 4 (N); WM=32, WN=32 -> FM=2, FN=4
    const int wm = (warp >> 2) * 32;
    const int wn = (warp & 3) * 32;
    const int m0 = (blockIdx.x >> 1) * G1_BM;
    const int nh = blockIdx.x & 1;                  // n-half: columns [nh*128, nh*128+128)
    const __half* qw1b = g_qw1 + (size_t)nh * G1_BN * CI;

    float acc[2][4][4];
    #pragma unroll
    for (int a = 0; a < 2; a++)
        #pragma unroll
        for (int b = 0; b < 4; b++)
            #pragma unroll
            for (int c = 0; c < 4; c++) acc[a][b][c] = 0.0f;

    auto cpA = [&](int kt, int buf) {
        #pragma unroll
        for (int i = 0; i < 2; i++) {               // 64 rows x 8 16B-vecs = 512 / 256 thr
            int idx = tid + i * 256, r = idx >> 3, c = (idx & 7) * 8;
            int gr = m0 + r;
            unsigned d = (unsigned)__cvta_generic_to_shared(As + (buf * G1_BM + r) * G1_LDS + c);
            const __half* g = g_qx + (size_t)(gr < NN ? gr : 0) * CI + kt * G1_BK + c;
            int sz = (gr < NN) ? 16 : 0;
            asm volatile("cp.async.cg.shared.global [%0], [%1], 16, %2;\n"
                         :: "r"(d), "l"(g), "r"(sz));
        }
    };
    auto cpB = [&](int kt, int buf) {
        #pragma unroll
        for (int i = 0; i < 4; i++) {               // 128 rows x 8 vecs = 1024 / 256 thr
            int idx = tid + i * 256, r = idx >> 3, c = (idx & 7) * 8;
            unsigned d = (unsigned)__cvta_generic_to_shared(Bs + (buf * G1_BN + r) * G1_LDS + c);
            const __half* g = qw1b + (size_t)r * CI + kt * G1_BK + c;
            asm volatile("cp.async.cg.shared.global [%0], [%1], 16;\n" :: "r"(d), "l"(g));
        }
    };

    cpA(0, 0); cpB(0, 0);
    asm volatile("cp.async.commit_group;\n");

    const int nk = CI / G1_BK;                      // 8
    for (int kt = 0; kt < nk; kt++) {
        const int cur = kt & 1;
        asm volatile("cp.async.wait_group 0;\n");
        __syncthreads();
        if (kt + 1 < nk) { cpA(kt + 1, cur ^ 1); cpB(kt + 1, cur ^ 1); }
        asm volatile("cp.async.commit_group;\n");

        const __half* Ab = As + cur * G1_BM * G1_LDS;
        const __half* Bb = Bs + cur * G1_BN * G1_LDS;
        #pragma unroll
        for (int ks = 0; ks < G1_BK / 16; ks++) {   // 4
            unsigned af[2][4], bf[4][2];
            #pragma unroll
            for (int fm = 0; fm < 2; fm++) {
                unsigned addr = (unsigned)__cvta_generic_to_shared(
                    Ab + (wm + fm * 16 + (lane & 15)) * G1_LDS + ks * 16 + (lane >> 4) * 8);
                asm volatile("ldmatrix.sync.aligned.m8n8.x4.shared.b16 {%0,%1,%2,%3}, [%4];"
                    : "=r"(af[fm][0]), "=r"(af[fm][1]), "=r"(af[fm][2]), "=r"(af[fm][3])
                    : "r"(addr));
            }
            #pragma unroll
            for (int p = 0; p < 2; p++) {           // n16 pair per x4 load
                unsigned addr = (unsigned)__cvta_generic_to_shared(
                    Bb + (wn + p * 16 + ((lane >> 4) & 1) * 8 + (lane & 7)) * G1_LDS
                       + ks * 16 + ((lane >> 3) & 1) * 8);
                asm volatile("ldmatrix.sync.aligned.m8n8.x4.shared.b16 {%0,%1,%2,%3}, [%4];"
                    : "=r"(bf[2 * p][0]), "=r"(bf[2 * p][1]),
                      "=r"(bf[2 * p + 1][0]), "=r"(bf[2 * p + 1][1])
                    : "r"(addr));
            }
            #pragma unroll
            for (int fm = 0; fm < 2; fm++)
                #pragma unroll
                for (int fn = 0; fn < 4; fn++) {
                    asm volatile(
                        "mma.sync.aligned.m16n8k16.row.col.f32.f16.f16.f32 "
                        "{%0,%1,%2,%3},{%4,%5,%6,%7},{%8,%9},{%0,%1,%2,%3};"
                        : "+f"(acc[fm][fn][0]), "+f"(acc[fm][fn][1]),
                          "+f"(acc[fm][fn][2]), "+f"(acc[fm][fn][3])
                        : "r"(af[fm][0]), "r"(af[fm][1]), "r"(af[fm][2]), "r"(af[fm][3]),
                          "r"(bf[fn][0]), "r"(bf[fn][1]));
                }
        }
    }

    // epilogue: scale+bias+relu, record max|h|, write fp16 (columns nh*128 + ...)
    const float cs = g_scales[1];
    float lmax = 0.0f;
    #pragma unroll
    for (int fm = 0; fm < 2; fm++)
        #pragma unroll
        for (int fn = 0; fn < 4; fn++) {
            int col = nh * G1_BN + wn + fn * 8 + (lane & 3) * 2;
            #pragma unroll
            for (int hh = 0; hh < 2; hh++) {
                int gr = m0 + wm + fm * 16 + (lane >> 2) + hh * 8;
                if (gr < NN) {
                    float v0 = acc[fm][fn][hh * 2 + 0] * cs + b1[col];
                    float v1 = acc[fm][fn][hh * 2 + 1] * cs + b1[col + 1];
                    v0 = fmaxf(v0, 0.0f); v1 = fmaxf(v1, 0.0f);
                    lmax = fmaxf(lmax, fmaxf(v0, v1));
                    *reinterpret_cast<__half2*>(g_h + (size_t)gr * CH + col) =
                        __floats2half2_rn(v0, v1);
                }
            }
        }
    #pragma unroll
    for (int o = 16; o > 0; o >>= 1) lmax = fmaxf(lmax, __shfl_xor_sync(0xffffffffu, lmax, o));
    if (lane == 0) atomicMax(&g_maxbits[3], __float_as_int(lmax));
}

// ---------------- GEMM2: fp16 pipe; epilogue folds dinv[src] into z ----------------
static constexpr int G2_BM = 128, G2_BN = 64, G2_BK = 64, G2_LDSH = 72;
static constexpr int SMEM2 = 2 * (G2_BM + G2_BN) * G2_LDSH * 2;   // 55296 B

__global__ void __launch_bounds__(256) gemm2_kernel(const float* __restrict__ b2) {
    extern __shared__ __align__(16) char sm2[];
    __half* As = reinterpret_cast<__half*>(sm2);          // [2][128][72]
    __half* Bs = As + 2 * G2_BM * G2_LDSH;                 // [2][64][72]

    const int tid = threadIdx.x, warp = tid >> 5, lane = tid & 31;
    const int wm = (warp >> 1) * 32;
    const int wn = (warp & 1) * 32;
    const int m0 = blockIdx.x * G2_BM;
    const float inv_a = g_scales[4];

    uint4 aregh[4];
    float acc[2][4][4];
    #pragma unroll
    for (int a = 0; a < 2; a++)
        #pragma unroll
        for (int b = 0; b < 4; b++)
            #pragma unroll
            for (int c = 0; c < 4; c++) acc[a][b][c] = 0.0f;

    auto loadA = [&](int k0) {
        #pragma unroll
        for (int i = 0; i < 4; i++) {
            int idx = tid + i * 256, r = idx >> 3, c = (idx & 7) << 3, gr = m0 + r;
            aregh[i] = (gr < NN)
                ? *reinterpret_cast<const uint4*>(g_h + (size_t)gr * CH + k0 + c)
                : make_uint4(0u, 0u, 0u, 0u);
        }
    };
    auto storeA = [&](int buf) {
        __half* base = As + buf * G2_BM * G2_LDSH;
        #pragma unroll
        for (int i = 0; i < 4; i++) {
            int idx = tid + i * 256, r = idx >> 3, c = (idx & 7) << 3;
            uint4 u = aregh[i], o;
            unsigned* ui = reinterpret_cast<unsigned*>(&u);
            unsigned* uo = reinterpret_cast<unsigned*>(&o);
            #pragma unroll
            for (int j = 0; j < 4; j++) {
                __half2 hv = *reinterpret_cast<const __half2*>(&ui[j]);
                float2 f = __half22float2(hv);
                uo[j] = packh2(qlevel_mul(f.x, inv_a), qlevel_mul(f.y, inv_a));
            }
            *reinterpret_cast<uint4*>(base + r * G2_LDSH + c) = o;
        }
    };
    auto cpB = [&](int k0, int buf) {
        #pragma unroll
        for (int i = 0; i < 2; i++) {
            int idx = tid + i * 256, r = idx >> 3, c = (idx & 7) << 3;
            unsigned d = (unsigned)__cvta_generic_to_shared(Bs + (buf * G2_BN + r) * G2_LDSH + c);
            const __half* g = g_qw2 + (size_t)r * CH + k0 + c;
            asm volatile("cp.async.cg.shared.global [%0], [%1], 16;\n" :: "r"(d), "l"(g));
        }
    };

    loadA(0);
    cpB(0, 0);
    asm volatile("cp.async.commit_group;\n");

    const int nk = CH / G2_BK;    // 4
    for (int kt = 0; kt < nk; kt++) {
        const int cur = kt & 1;
        storeA(cur);
        asm volatile("cp.async.wait_group 0;\n");
        __syncthreads();
        if (kt + 1 < nk) { loadA((kt + 1) * G2_BK); cpB((kt + 1) * G2_BK, cur ^ 1); }
        asm volatile("cp.async.commit_group;\n");

        const __half* Ab = As + cur * G2_BM * G2_LDSH;
        const __half* Bb = Bs + cur * G2_BN * G2_LDSH;
        #pragma unroll
        for (int ks = 0; ks < 4; ks++) {
            unsigned af[2][4], bf[4][2];
            #pragma unroll
            for (int fm = 0; fm < 2; fm++) {
                unsigned addr = (unsigned)__cvta_generic_to_shared(
                    Ab + (wm + fm * 16 + (lane & 15)) * G2_LDSH + ks * 16 + (lane >> 4) * 8);
                asm volatile("ldmatrix.sync.aligned.m8n8.x4.shared.b16 {%0,%1,%2,%3}, [%4];"
                    : "=r"(af[fm][0]), "=r"(af[fm][1]), "=r"(af[fm][2]), "=r"(af[fm][3])
                    : "r"(addr));
            }
            #pragma unroll
            for (int p = 0; p < 2; p++) {
                unsigned addr = (unsigned)__cvta_generic_to_shared(
                    Bb + (wn + p * 16 + ((lane >> 4) & 1) * 8 + (lane & 7)) * G2_LDSH
                       + ks * 16 + ((lane >> 3) & 1) * 8);
                asm volatile("ldmatrix.sync.aligned.m8n8.x4.shared.b16 {%0,%1,%2,%3}, [%4];"
                    : "=r"(bf[2 * p][0]), "=r"(bf[2 * p][1]),
                      "=r"(bf[2 * p + 1][0]), "=r"(bf[2 * p + 1][1])
                    : "r"(addr));
            }
            #pragma unroll
            for (int fm = 0; fm < 2; fm++)
                #pragma unroll
                for (int fn = 0; fn < 4; fn++) {
                    asm volatile(
                        "mma.sync.aligned.m16n8k16.row.col.f32.f16.f16.f32 "
                        "{%0,%1,%2,%3},{%4,%5,%6,%7},{%8,%9},{%0,%1,%2,%3};"
                        : "+f"(acc[fm][fn][0]), "+f"(acc[fm][fn][1]),
                          "+f"(acc[fm][fn][2]), "+f"(acc[fm][fn][3])
                        : "r"(af[fm][0]), "r"(af[fm][1]), "r"(af[fm][2]), "r"(af[fm][3]),
                          "r"(bf[fn][0]), "r"(bf[fn][1]));
                }
        }
    }

    // z' = (fq(h)@qw2^T * cs + b2) * dinv[row]   (dinv[src] folded here)
    const float cs = g_scales[5];
    #pragma unroll
    for (int fm = 0; fm < 2; fm++)
        #pragma unroll
        for (int fn = 0; fn < 4; fn++) {
            int col = wn + fn * 8 + (lane & 3) * 2;
            #pragma unroll
            for (int hh = 0; hh < 2; hh++) {
                int gr = m0 + wm + fm * 16 + (lane >> 2) + hh * 8;
                if (gr < NN) {
                    float dv = g_dinv[gr];
                    #pragma unroll
                    for (int j = 0; j < 2; j++) {
                        int gc = col + j;
                        if (gc < CO)
                            g_z[(size_t)gr * CO + gc] =
                                (acc[fm][fn][hh * 2 + j] * cs + b2[gc]) * dv;
                    }
                }
            }
        }
}

// ---------------- init for propagation ----------------
__global__ void zero_kernel() {
    int i = blockIdx.x * blockDim.x + threadIdx.x;
    if (i < NN * CO / 4) reinterpret_cast<float4*>(g_accum)[i] = make_float4(0.f, 0.f, 0.f, 0.f);
    if (i < NN) g_deg[i] = 0.0f;
}

// ---------------- graph propagation ----------------
__global__ void degree_kernel(const int* __restrict__ ei) {
    int e = blockIdx.x * blockDim.x + threadIdx.x;
    if (e < NE) atomicAdd(&g_deg[ei[NE + e]], 1.0f);
}
__global__ void dinv_kernel() {
    int i = blockIdx.x * blockDim.x + threadIdx.x;
    if (i < NN) {
        float d = g_deg[i];
        g_dinv[i] = (d > 0.0f) ? rsqrtf(fmaxf(d, 1.0f)) : 0.0f;
    }
}
// Warp-cooperative propagate: 16 edges per warp; 160 (edge, float4) tasks / 32 lanes.
// z already carries dinv[src]; dinv[dst] is applied in logsoftmax.
__global__ void propagate_kernel(const int* __restrict__ ei) {
    int gwarp = (blockIdx.x * blockDim.x + threadIdx.x) >> 5;
    int lane = threadIdx.x & 31;
    int base = gwarp * 16;
    if (base >= NE) return;
    int idxv = ei[((lane < 16) ? 0 : NE) + base + (lane & 15)];
    #pragma unroll
    for (int i = 0; i < 5; i++) {
        int task = lane + 32 * i;  // 0..159
        int e = task / 10, ch = task - e * 10;
        int srce = __shfl_sync(0xffffffffu, idxv, e);
        int dste = __shfl_sync(0xffffffffu, idxv, e + 16);
        float4 v = *reinterpret_cast<const float4*>(g_z + (size_t)srce * CO + ch * 4);
        float* p = g_accum + (size_t)dste * CO + ch * 4;
        asm volatile("red.global.add.v4.f32 [%0], {%1,%2,%3,%4};"
                     :: "l"(p), "f"(v.x), "f"(v.y), "f"(v.z), "f"(v.w)
                     : "memory");
    }
}

// ---------------- log-softmax (warp per node row of 40; applies dinv[dst]) ----------------
__global__ void logsoftmax_kernel(float* __restrict__ out) {
    int gw = (blockIdx.x * blockDim.x + threadIdx.x) >> 5;
    int lane = threadIdx.x & 31;
    if (gw >= NN) return;
    const float dv = g_dinv[gw];
    const float* row = g_accum + (size_t)gw * CO;
    float x1 = row[lane] * dv;
    float x2 = (lane < 8) ? row[32 + lane] * dv : -3.402823466e+38f;
    float m = fmaxf(x1, x2);
    #pragma unroll
    for (int o = 16; o > 0; o >>= 1) m = fmaxf(m, __shfl_xor_sync(0xffffffffu, m, o));
    float s = expf(x1 - m) + ((lane < 8) ? expf(x2 - m) : 0.0f);
    #pragma unroll
    for (int o = 16; o > 0; o >>= 1) s += __shfl_xor_sync(0xffffffffu, s, o);
    float lse = m + logf(s);
    float* o = out + (size_t)gw * CO;
    o[lane] = x1 - lse;
    if (lane < 8) o[32 + lane] = x2 - lse;
}

// ---------------- launch (gemm1 at slot #4 for the ncu capture) ----------------
extern "C" void kernel_launch(void* const* d_in, const int* in_sizes, int n_in,
                              void* d_out, int out_size) {
    const float* x  = (const float*)d_in[0];
    const int*   ei = (const int*)d_in[1];
    const float* w1 = (const float*)d_in[2];
    const float* b1 = (const float*)d_in[3];
    const float* w2 = (const float*)d_in[4];
    const float* b2 = (const float*)d_in[5];
    float* out = (float*)d_out;

    cudaFuncSetAttribute(gemm1_kernel, cudaFuncAttributeMaxDynamicSharedMemorySize, SMEM1);
    cudaFuncSetAttribute(gemm2_kernel, cudaFuncAttributeMaxDynamicSharedMemorySize, SMEM2);

    absmax_all_kernel<<<2048, 256>>>(x, w1, w2);                        // 1
    finalize1_kernel<<<1, 1>>>();                                       // 2
    quant_all_kernel<<<2048, 256>>>(x, w1, w2);                         // 3
    gemm1_kernel<<<DIVUP(NN, G1_BM) * 2, 256, SMEM1>>>(b1);             // 4  <- profiled
    finalize2_kernel<<<1, 1>>>();                                       // 5
    zero_kernel<<<DIVUP(NN * CO / 4, 256), 256>>>();                    // 6
    degree_kernel<<<DIVUP(NE, 256), 256>>>(ei);                         // 7
    dinv_kernel<<<DIVUP(NN, 256), 256>>>();                            // 8
    gemm2_kernel<<<DIVUP(NN, G2_BM), 256, SMEM2>>>(b2);                 // 9 (needs dinv)
    propagate_kernel<<<DIVUP(NE / 16 * 32, 256), 256>>>(ei);            // 10
    logsoftmax_kernel<<<DIVUP(NN * 32, 256), 256>>>(out);               // 11
}

// round 15
// speedup vs baseline: 1.0950x; 1.0291x over previous
#include <cuda_runtime.h>
#include <cuda_bf16.h>
#include <cuda_fp16.h>
#include <cstdint>

#define DIVUP(a,b) (((a)+(b)-1)/(b))

static constexpr int NN = 100000;   // nodes
static constexpr int NE = 1600000;  // edges (divisible by 16)
static constexpr int CI = 512;      // in_channels
static constexpr int CH = 256;      // hidden
static constexpr int CO = 40;       // out_channels
static constexpr int CO_PAD = 64;   // padded out channels for GEMM2

// ---------------- scratch (static device globals; no allocation) ----------------
__device__ __align__(16) __half g_qx[(size_t)NN * CI];     // quantized x levels (fp16)
__device__ __align__(16) __half g_qw1[CH * CI];            // quantized w1 levels (fp16)
__device__ __align__(16) __half g_qw2[CO_PAD * CH];        // quantized w2 levels (fp16)
__device__ __align__(16) __half g_h[(size_t)NN * CH];      // hidden activations (fp16)
__device__ __align__(16) float g_z[(size_t)NN * CO];       // dinv[src]-scaled logits
__device__ __align__(16) float g_accum[(size_t)NN * CO];   // propagation accumulator
__device__ float g_deg[NN];          // zeroed by dinv loop each replay
__device__ float g_dinv[NN];
__device__ int   g_maxbits[4];       // 0:|x| 1:|w1| 2:|w2| 3:|h| (finalize resets)
// scales: 0:1/sx 1:sx*sw1 2:1/sw1 3:1/sw2 4:1/sh 5:sh*sw2 6:sw2
__device__ float g_scales[8];

__device__ __forceinline__ float qlevel_mul(float x, float inv) {
    float q = rintf(x * inv);
    return fminf(fmaxf(q, -128.0f), 127.0f);
}
__device__ __forceinline__ unsigned packh2(float a, float b) {
    __half2 t = __floats2half2_rn(a, b);
    return *reinterpret_cast<unsigned*>(&t);
}

// ---- fused: abs-max(x,w1,w2) + zero(g_accum) + degree atomics ----
// degree relies on g_deg == 0 on entry (static init on first run; dinv loop in
// quant_all resets it after consuming, keeping graph replays deterministic).
__global__ void absmax_all_kernel(const float* __restrict__ x,
                                  const float* __restrict__ w1,
                                  const float* __restrict__ w2,
                                  const int* __restrict__ ei) {
    const size_t stride = (size_t)gridDim.x * blockDim.x;
    const size_t t0 = (size_t)blockIdx.x * blockDim.x + threadIdx.x;
    // zero accumulator (16MB) — independent of everything below
    for (size_t i = t0; i < (size_t)NN * CO / 4; i += stride)
        reinterpret_cast<float4*>(g_accum)[i] = make_float4(0.f, 0.f, 0.f, 0.f);
    // degree atomics (overlap with DRAM-bound absmax)
    for (size_t e = t0; e < NE; e += stride)
        atomicAdd(&g_deg[ei[NE + e]], 1.0f);

    float m0 = 0.f, m1 = 0.f, m2 = 0.f;
    #pragma unroll 4
    for (size_t i = t0; i < (size_t)NN * CI / 4; i += stride) {
        float4 v = reinterpret_cast<const float4*>(x)[i];
        m0 = fmaxf(m0, fmaxf(fmaxf(fabsf(v.x), fabsf(v.y)), fmaxf(fabsf(v.z), fabsf(v.w))));
    }
    for (size_t i = t0; i < (size_t)CH * CI / 4; i += stride) {
        float4 v = reinterpret_cast<const float4*>(w1)[i];
        m1 = fmaxf(m1, fmaxf(fmaxf(fabsf(v.x), fabsf(v.y)), fmaxf(fabsf(v.z), fabsf(v.w))));
    }
    for (size_t i = t0; i < (size_t)CO * CH / 4; i += stride) {
        float4 v = reinterpret_cast<const float4*>(w2)[i];
        m2 = fmaxf(m2, fmaxf(fmaxf(fabsf(v.x), fabsf(v.y)), fmaxf(fabsf(v.z), fabsf(v.w))));
    }
    #pragma unroll
    for (int o = 16; o > 0; o >>= 1) {
        m0 = fmaxf(m0, __shfl_xor_sync(0xffffffffu, m0, o));
        m1 = fmaxf(m1, __shfl_xor_sync(0xffffffffu, m1, o));
        m2 = fmaxf(m2, __shfl_xor_sync(0xffffffffu, m2, o));
    }
    if ((threadIdx.x & 31) == 0) {
        atomicMax(&g_maxbits[0], __float_as_int(m0));
        if (m1 > 0.f) atomicMax(&g_maxbits[1], __float_as_int(m1));
        if (m2 > 0.f) atomicMax(&g_maxbits[2], __float_as_int(m2));
    }
}

__global__ void finalize1_kernel() {
    float sx  = __int_as_float(g_maxbits[0]) / 127.0f + 1e-12f;
    float sw1 = __int_as_float(g_maxbits[1]) / 127.0f + 1e-12f;
    float sw2 = __int_as_float(g_maxbits[2]) / 127.0f + 1e-12f;
    g_scales[0] = 1.0f / sx;
    g_scales[1] = sx * sw1;
    g_scales[2] = 1.0f / sw1;
    g_scales[3] = 1.0f / sw2;
    g_scales[6] = sw2;
    g_maxbits[0] = 0; g_maxbits[1] = 0; g_maxbits[2] = 0;   // reset for graph replay
}
__global__ void finalize2_kernel() {
    float sh = __int_as_float(g_maxbits[3]) / 127.0f + 1e-12f;
    g_scales[4] = 1.0f / sh;
    g_scales[5] = sh * g_scales[6];
    g_maxbits[3] = 0;                                        // reset for graph replay
}

// ---- fused: quantize x/w1/w2 + dinv (consumes + resets g_deg) ----
__global__ void quant_all_kernel(const float* __restrict__ x,
                                 const float* __restrict__ w1,
                                 const float* __restrict__ w2) {
    const size_t stride = (size_t)gridDim.x * blockDim.x;
    const size_t t0 = (size_t)blockIdx.x * blockDim.x + threadIdx.x;
    const float invx = g_scales[0], invw1 = g_scales[2], invw2 = g_scales[3];
    // dinv from degree; reset degree for the next replay
    for (size_t i = t0; i < NN; i += stride) {
        float d = g_deg[i];
        g_dinv[i] = (d > 0.0f) ? rsqrtf(fmaxf(d, 1.0f)) : 0.0f;
        g_deg[i] = 0.0f;
    }
    #pragma unroll 2
    for (size_t i = t0; i < (size_t)NN * CI / 4; i += stride) {
        float4 v = reinterpret_cast<const float4*>(x)[i];
        uint2 o;
        o.x = packh2(qlevel_mul(v.x, invx), qlevel_mul(v.y, invx));
        o.y = packh2(qlevel_mul(v.z, invx), qlevel_mul(v.w, invx));
        reinterpret_cast<uint2*>(g_qx)[i] = o;
    }
    for (size_t i = t0; i < (size_t)CH * CI / 4; i += stride) {
        float4 v = reinterpret_cast<const float4*>(w1)[i];
        uint2 o;
        o.x = packh2(qlevel_mul(v.x, invw1), qlevel_mul(v.y, invw1));
        o.y = packh2(qlevel_mul(v.z, invw1), qlevel_mul(v.w, invw1));
        reinterpret_cast<uint2*>(g_qw1)[i] = o;
    }
    for (size_t i = t0; i < (size_t)CO_PAD * CH; i += stride) {
        int r = (int)(i / CH), c = (int)(i % CH);
        float v = (r < CO) ? qlevel_mul(w2[r * CH + c], invw2) : 0.0f;
        g_qw2[i] = __float2half_rn(v);
    }
}

// ---------------- GEMM1: fp16 HMMA, BK=64 2-stage, N split, 3 CTAs/SM ----------------
// h = relu( (qx @ qw1^T) * sx*sw1 + b1 ), records max|h|.
static constexpr int G1_BM = 64, G1_BN = 128, G1_BK = 64, G1_LDS = 72;
static constexpr int SMEM1 = 2 * (G1_BM + G1_BN) * G1_LDS * 2;   // 55296 B -> 3 CTAs/SM

__global__ void __launch_bounds__(256, 3) gemm1_kernel(const float* __restrict__ b1) {
    extern __shared__ __align__(16) char sm[];
    __half* As = reinterpret_cast<__half*>(sm);     // [2][64][72]
    __half* Bs = As + 2 * G1_BM * G1_LDS;           // [2][128][72]

    const int tid = threadIdx.x, warp = tid >> 5, lane = tid & 31;
    const int wm = (warp >> 2) * 32;
    const int wn = (warp & 3) * 32;
    const int m0 = (blockIdx.x >> 1) * G1_BM;
    const int nh = blockIdx.x & 1;                  // n-half: columns [nh*128, nh*128+128)
    const __half* qw1b = g_qw1 + (size_t)nh * G1_BN * CI;

    float acc[2][4][4];
    #pragma unroll
    for (int a = 0; a < 2; a++)
        #pragma unroll
        for (int b = 0; b < 4; b++)
            #pragma unroll
            for (int c = 0; c < 4; c++) acc[a][b][c] = 0.0f;

    auto cpA = [&](int kt, int buf) {
        #pragma unroll
        for (int i = 0; i < 2; i++) {
            int idx = tid + i * 256, r = idx >> 3, c = (idx & 7) * 8;
            int gr = m0 + r;
            unsigned d = (unsigned)__cvta_generic_to_shared(As + (buf * G1_BM + r) * G1_LDS + c);
            const __half* g = g_qx + (size_t)(gr < NN ? gr : 0) * CI + kt * G1_BK + c;
            int sz = (gr < NN) ? 16 : 0;
            asm volatile("cp.async.cg.shared.global [%0], [%1], 16, %2;\n"
                         :: "r"(d), "l"(g), "r"(sz));
        }
    };
    auto cpB = [&](int kt, int buf) {
        #pragma unroll
        for (int i = 0; i < 4; i++) {
            int idx = tid + i * 256, r = idx >> 3, c = (idx & 7) * 8;
            unsigned d = (unsigned)__cvta_generic_to_shared(Bs + (buf * G1_BN + r) * G1_LDS + c);
            const __half* g = qw1b + (size_t)r * CI + kt * G1_BK + c;
            asm volatile("cp.async.cg.shared.global [%0], [%1], 16;\n" :: "r"(d), "l"(g));
        }
    };

    cpA(0, 0); cpB(0, 0);
    asm volatile("cp.async.commit_group;\n");

    const int nk = CI / G1_BK;                      // 8
    for (int kt = 0; kt < nk; kt++) {
        const int cur = kt & 1;
        asm volatile("cp.async.wait_group 0;\n");
        __syncthreads();
        if (kt + 1 < nk) { cpA(kt + 1, cur ^ 1); cpB(kt + 1, cur ^ 1); }
        asm volatile("cp.async.commit_group;\n");

        const __half* Ab = As + cur * G1_BM * G1_LDS;
        const __half* Bb = Bs + cur * G1_BN * G1_LDS;
        #pragma unroll
        for (int ks = 0; ks < G1_BK / 16; ks++) {   // 4
            unsigned af[2][4], bf[4][2];
            #pragma unroll
            for (int fm = 0; fm < 2; fm++) {
                unsigned addr = (unsigned)__cvta_generic_to_shared(
                    Ab + (wm + fm * 16 + (lane & 15)) * G1_LDS + ks * 16 + (lane >> 4) * 8);
                asm volatile("ldmatrix.sync.aligned.m8n8.x4.shared.b16 {%0,%1,%2,%3}, [%4];"
                    : "=r"(af[fm][0]), "=r"(af[fm][1]), "=r"(af[fm][2]), "=r"(af[fm][3])
                    : "r"(addr));
            }
            #pragma unroll
            for (int p = 0; p < 2; p++) {
                unsigned addr = (unsigned)__cvta_generic_to_shared(
                    Bb + (wn + p * 16 + ((lane >> 4) & 1) * 8 + (lane & 7)) * G1_LDS
                       + ks * 16 + ((lane >> 3) & 1) * 8);
                asm volatile("ldmatrix.sync.aligned.m8n8.x4.shared.b16 {%0,%1,%2,%3}, [%4];"
                    : "=r"(bf[2 * p][0]), "=r"(bf[2 * p][1]),
                      "=r"(bf[2 * p + 1][0]), "=r"(bf[2 * p + 1][1])
                    : "r"(addr));
            }
            #pragma unroll
            for (int fm = 0; fm < 2; fm++)
                #pragma unroll
                for (int fn = 0; fn < 4; fn++) {
                    asm volatile(
                        "mma.sync.aligned.m16n8k16.row.col.f32.f16.f16.f32 "
                        "{%0,%1,%2,%3},{%4,%5,%6,%7},{%8,%9},{%0,%1,%2,%3};"
                        : "+f"(acc[fm][fn][0]), "+f"(acc[fm][fn][1]),
                          "+f"(acc[fm][fn][2]), "+f"(acc[fm][fn][3])
                        : "r"(af[fm][0]), "r"(af[fm][1]), "r"(af[fm][2]), "r"(af[fm][3]),
                          "r"(bf[fn][0]), "r"(bf[fn][1]));
                }
        }
    }

    const float cs = g_scales[1];
    float lmax = 0.0f;
    #pragma unroll
    for (int fm = 0; fm < 2; fm++)
        #pragma unroll
        for (int fn = 0; fn < 4; fn++) {
            int col = nh * G1_BN + wn + fn * 8 + (lane & 3) * 2;
            #pragma unroll
            for (int hh = 0; hh < 2; hh++) {
                int gr = m0 + wm + fm * 16 + (lane >> 2) + hh * 8;
                if (gr < NN) {
                    float v0 = acc[fm][fn][hh * 2 + 0] * cs + b1[col];
                    float v1 = acc[fm][fn][hh * 2 + 1] * cs + b1[col + 1];
                    v0 = fmaxf(v0, 0.0f); v1 = fmaxf(v1, 0.0f);
                    lmax = fmaxf(lmax, fmaxf(v0, v1));
                    *reinterpret_cast<__half2*>(g_h + (size_t)gr * CH + col) =
                        __floats2half2_rn(v0, v1);
                }
            }
        }
    #pragma unroll
    for (int o = 16; o > 0; o >>= 1) lmax = fmaxf(lmax, __shfl_xor_sync(0xffffffffu, lmax, o));
    if (lane == 0) atomicMax(&g_maxbits[3], __float_as_int(lmax));
}

// ---------------- GEMM2: fp16 pipe, 2 CTAs/SM; epilogue folds dinv[src] ----------------
static constexpr int G2_BM = 128, G2_BN = 64, G2_BK = 64, G2_LDSH = 72;
static constexpr int SMEM2 = 2 * (G2_BM + G2_BN) * G2_LDSH * 2;   // 55296 B

__global__ void __launch_bounds__(256, 2) gemm2_kernel(const float* __restrict__ b2) {
    extern __shared__ __align__(16) char sm2[];
    __half* As = reinterpret_cast<__half*>(sm2);          // [2][128][72]
    __half* Bs = As + 2 * G2_BM * G2_LDSH;                 // [2][64][72]

    const int tid = threadIdx.x, warp = tid >> 5, lane = tid & 31;
    const int wm = (warp >> 1) * 32;
    const int wn = (warp & 1) * 32;
    const int m0 = blockIdx.x * G2_BM;
    const float inv_a = g_scales[4];

    uint4 aregh[4];
    float acc[2][4][4];
    #pragma unroll
    for (int a = 0; a < 2; a++)
        #pragma unroll
        for (int b = 0; b < 4; b++)
            #pragma unroll
            for (int c = 0; c < 4; c++) acc[a][b][c] = 0.0f;

    auto loadA = [&](int k0) {
        #pragma unroll
        for (int i = 0; i < 4; i++) {
            int idx = tid + i * 256, r = idx >> 3, c = (idx & 7) << 3, gr = m0 + r;
            aregh[i] = (gr < NN)
                ? *reinterpret_cast<const uint4*>(g_h + (size_t)gr * CH + k0 + c)
                : make_uint4(0u, 0u, 0u, 0u);
        }
    };
    auto storeA = [&](int buf) {
        __half* base = As + buf * G2_BM * G2_LDSH;
        #pragma unroll
        for (int i = 0; i < 4; i++) {
            int idx = tid + i * 256, r = idx >> 3, c = (idx & 7) << 3;
            uint4 u = aregh[i], o;
            unsigned* ui = reinterpret_cast<unsigned*>(&u);
            unsigned* uo = reinterpret_cast<unsigned*>(&o);
            #pragma unroll
            for (int j = 0; j < 4; j++) {
                __half2 hv = *reinterpret_cast<const __half2*>(&ui[j]);
                float2 f = __half22float2(hv);
                uo[j] = packh2(qlevel_mul(f.x, inv_a), qlevel_mul(f.y, inv_a));
            }
            *reinterpret_cast<uint4*>(base + r * G2_LDSH + c) = o;
        }
    };
    auto cpB = [&](int k0, int buf) {
        #pragma unroll
        for (int i = 0; i < 2; i++) {
            int idx = tid + i * 256, r = idx >> 3, c = (idx & 7) << 3;
            unsigned d = (unsigned)__cvta_generic_to_shared(Bs + (buf * G2_BN + r) * G2_LDSH + c);
            const __half* g = g_qw2 + (size_t)r * CH + k0 + c;
            asm volatile("cp.async.cg.shared.global [%0], [%1], 16;\n" :: "r"(d), "l"(g));
        }
    };

    loadA(0);
    cpB(0, 0);
    asm volatile("cp.async.commit_group;\n");

    const int nk = CH / G2_BK;    // 4
    for (int kt = 0; kt < nk; kt++) {
        const int cur = kt & 1;
        storeA(cur);
        asm volatile("cp.async.wait_group 0;\n");
        __syncthreads();
        if (kt + 1 < nk) { loadA((kt + 1) * G2_BK); cpB((kt + 1) * G2_BK, cur ^ 1); }
        asm volatile("cp.async.commit_group;\n");

        const __half* Ab = As + cur * G2_BM * G2_LDSH;
        const __half* Bb = Bs + cur * G2_BN * G2_LDSH;
        #pragma unroll
        for (int ks = 0; ks < 4; ks++) {
            unsigned af[2][4], bf[4][2];
            #pragma unroll
            for (int fm = 0; fm < 2; fm++) {
                unsigned addr = (unsigned)__cvta_generic_to_shared(
                    Ab + (wm + fm * 16 + (lane & 15)) * G2_LDSH + ks * 16 + (lane >> 4) * 8);
                asm volatile("ldmatrix.sync.aligned.m8n8.x4.shared.b16 {%0,%1,%2,%3}, [%4];"
                    : "=r"(af[fm][0]), "=r"(af[fm][1]), "=r"(af[fm][2]), "=r"(af[fm][3])
                    : "r"(addr));
            }
            #pragma unroll
            for (int p = 0; p < 2; p++) {
                unsigned addr = (unsigned)__cvta_generic_to_shared(
                    Bb + (wn + p * 16 + ((lane >> 4) & 1) * 8 + (lane & 7)) * G2_LDSH
                       + ks * 16 + ((lane >> 3) & 1) * 8);
                asm volatile("ldmatrix.sync.aligned.m8n8.x4.shared.b16 {%0,%1,%2,%3}, [%4];"
                    : "=r"(bf[2 * p][0]), "=r"(bf[2 * p][1]),
                      "=r"(bf[2 * p + 1][0]), "=r"(bf[2 * p + 1][1])
                    : "r"(addr));
            }
            #pragma unroll
            for (int fm = 0; fm < 2; fm++)
                #pragma unroll
                for (int fn = 0; fn < 4; fn++) {
                    asm volatile(
                        "mma.sync.aligned.m16n8k16.row.col.f32.f16.f16.f32 "
                        "{%0,%1,%2,%3},{%4,%5,%6,%7},{%8,%9},{%0,%1,%2,%3};"
                        : "+f"(acc[fm][fn][0]), "+f"(acc[fm][fn][1]),
                          "+f"(acc[fm][fn][2]), "+f"(acc[fm][fn][3])
                        : "r"(af[fm][0]), "r"(af[fm][1]), "r"(af[fm][2]), "r"(af[fm][3]),
                          "r"(bf[fn][0]), "r"(bf[fn][1]));
                }
        }
    }

    // z' = (fq(h)@qw2^T * cs + b2) * dinv[row]   (dinv[src] folded here)
    const float cs = g_scales[5];
    #pragma unroll
    for (int fm = 0; fm < 2; fm++)
        #pragma unroll
        for (int fn = 0; fn < 4; fn++) {
            int col = wn + fn * 8 + (lane & 3) * 2;
            #pragma unroll
            for (int hh = 0; hh < 2; hh++) {
                int gr = m0 + wm + fm * 16 + (lane >> 2) + hh * 8;
                if (gr < NN) {
                    float dv = g_dinv[gr];
                    #pragma unroll
                    for (int j = 0; j < 2; j++) {
                        int gc = col + j;
                        if (gc < CO)
                            g_z[(size_t)gr * CO + gc] =
                                (acc[fm][fn][hh * 2 + j] * cs + b2[gc]) * dv;
                    }
                }
            }
        }
}

// ---------------- graph propagation ----------------
// Warp-cooperative: 16 edges per warp; 160 (edge, float4) tasks / 32 lanes.
// z carries dinv[src]; dinv[dst] applied in logsoftmax.
__global__ void propagate_kernel(const int* __restrict__ ei) {
    int gwarp = (blockIdx.x * blockDim.x + threadIdx.x) >> 5;
    int lane = threadIdx.x & 31;
    int base = gwarp * 16;
    if (base >= NE) return;
    int idxv = ei[((lane < 16) ? 0 : NE) + base + (lane & 15)];
    #pragma unroll
    for (int i = 0; i < 5; i++) {
        int task = lane + 32 * i;  // 0..159
        int e = task / 10, ch = task - e * 10;
        int srce = __shfl_sync(0xffffffffu, idxv, e);
        int dste = __shfl_sync(0xffffffffu, idxv, e + 16);
        float4 v = *reinterpret_cast<const float4*>(g_z + (size_t)srce * CO + ch * 4);
        float* p = g_accum + (size_t)dste * CO + ch * 4;
        asm volatile("red.global.add.v4.f32 [%0], {%1,%2,%3,%4};"
                     :: "l"(p), "f"(v.x), "f"(v.y), "f"(v.z), "f"(v.w)
                     : "memory");
    }
}

// ---------------- log-softmax (warp per node row of 40; applies dinv[dst]) ----------------
__global__ void logsoftmax_kernel(float* __restrict__ out) {
    int gw = (blockIdx.x * blockDim.x + threadIdx.x) >> 5;
    int lane = threadIdx.x & 31;
    if (gw >= NN) return;
    const float dv = g_dinv[gw];
    const float* row = g_accum + (size_t)gw * CO;
    float x1 = row[lane] * dv;
    float x2 = (lane < 8) ? row[32 + lane] * dv : -3.402823466e+38f;
    float m = fmaxf(x1, x2);
    #pragma unroll
    for (int o = 16; o > 0; o >>= 1) m = fmaxf(m, __shfl_xor_sync(0xffffffffu, m, o));
    float s = expf(x1 - m) + ((lane < 8) ? expf(x2 - m) : 0.0f);
    #pragma unroll
    for (int o = 16; o > 0; o >>= 1) s += __shfl_xor_sync(0xffffffffu, s, o);
    float lse = m + logf(s);
    float* o = out + (size_t)gw * CO;
    o[lane] = x1 - lse;
    if (lane < 8) o[32 + lane] = x2 - lse;
}

// ---------------- launch (gemm1 at slot #4 for the ncu capture) ----------------
extern "C" void kernel_launch(void* const* d_in, const int* in_sizes, int n_in,
                              void* d_out, int out_size) {
    const float* x  = (const float*)d_in[0];
    const int*   ei = (const int*)d_in[1];
    const float* w1 = (const float*)d_in[2];
    const float* b1 = (const float*)d_in[3];
    const float* w2 = (const float*)d_in[4];
    const float* b2 = (const float*)d_in[5];
    float* out = (float*)d_out;

    cudaFuncSetAttribute(gemm1_kernel, cudaFuncAttributeMaxDynamicSharedMemorySize, SMEM1);
    cudaFuncSetAttribute(gemm2_kernel, cudaFuncAttributeMaxDynamicSharedMemorySize, SMEM2);

    absmax_all_kernel<<<2048, 256>>>(x, w1, w2, ei);                    // 1 (+zero,+degree)
    finalize1_kernel<<<1, 1>>>();                                       // 2
    quant_all_kernel<<<2048, 256>>>(x, w1, w2);                         // 3 (+dinv)
    gemm1_kernel<<<DIVUP(NN, G1_BM) * 2, 256, SMEM1>>>(b1);             // 4  <- profiled
    finalize2_kernel<<<1, 1>>>();                                       // 5
    gemm2_kernel<<<DIVUP(NN, G2_BM), 256, SMEM2>>>(b2);                 // 6
    propagate_kernel<<<DIVUP(NE / 16 * 32, 256), 256>>>(ei);            // 7
    logsoftmax_kernel<<<DIVUP(NN * 32, 256), 256>>>(out);               // 8
}